// round 14
// baseline (speedup 1.0000x reference)
#include <cuda_runtime.h>
#include <math.h>

#define Bq 2
#define Lq 1024
#define Aq 14
#define Kq 30
#define NRBF 16
#define NPEq 16
#define EFq 128
#define EDGEIN (NPEq + NRBF*Aq*Aq)   /* 3152 */
#define NKQ4 (EDGEIN/4)              /* 788 */
#define NE (Bq*Lq*Kq*EFq)
#define NK (Bq*Lq*Kq)
#define PADF 36                      /* floats per slot: 32 data + 4 pad (144B) */
#define NPACKBLK ((NKQ4*EFq + 255)/256)   /* 394 */

typedef unsigned long long ull;

__device__ int    g_Eidx[Bq*Lq*Kq];
__device__ float4 g_W4[NKQ4*EFq];    /* g_W4[kq*128+f] = {W[f][4kq..4kq+3]} */

// ---------------- packed f32x2 helpers ----------------
__device__ __forceinline__ ull fma2(ull a, ull b, ull c){
    ull d; asm("fma.rn.f32x2 %0,%1,%2,%3;" : "=l"(d) : "l"(a),"l"(b),"l"(c)); return d;
}
__device__ __forceinline__ ull rep2(float x){
    ull d; asm("mov.b64 %0,{%1,%1};" : "=l"(d) : "f"(x)); return d;
}
__device__ __forceinline__ ull pack2(float lo, float hi){
    ull d; asm("mov.b64 %0,{%1,%2};" : "=l"(d) : "f"(lo),"f"(hi)); return d;
}
__device__ __forceinline__ void unpack2(ull v, float& lo, float& hi){
    asm("mov.b64 {%0,%1},%2;" : "=f"(lo),"=f"(hi) : "l"(v));
}

// ---------------------------------------------------------------------------
// Prep kernel: blocks [0,NPACKBLK) pack W; blocks [NPACKBLK, +2048) do KNN.
// ---------------------------------------------------------------------------
__global__ void prep_kernel(const float* __restrict__ W,
                            const float* __restrict__ X,
                            const float* __restrict__ mask,
                            float* __restrict__ outIdxF) {
    __shared__ float sD[Lq];
    __shared__ float smax[8];
    __shared__ unsigned long long red[8];

    if (blockIdx.x < NPACKBLK) {
        int idx = blockIdx.x * 256 + threadIdx.x;
        if (idx < NKQ4 * EFq) {
            int kq = idx >> 7, f = idx & 127;
            const float* src = W + f * EDGEIN + kq * 4;
            g_W4[idx] = make_float4(src[0], src[1], src[2], src[3]);
        }
        return;
    }

    const int bi  = blockIdx.x - NPACKBLK;
    const int b   = bi / Lq;
    const int tid = threadIdx.x;

    const float mi  = mask[bi];
    const float xi0 = X[(bi*Aq + 1)*3 + 0];
    const float xi1 = X[(bi*Aq + 1)*3 + 1];
    const float xi2 = X[(bi*Aq + 1)*3 + 2];

    float lmax = 0.f;
    for (int j = tid; j < Lq; j += 256) {
        const float* xj = X + ((b*Lq + j)*Aq + 1)*3;
        float dx = xi0 - xj[0], dy = xi1 - xj[1], dz = xi2 - xj[2];
        float m2 = mi * mask[b*Lq + j];
        float D  = m2 * sqrtf(dx*dx + dy*dy + dz*dz + 1e-6f);
        sD[j] = D;
        lmax = fmaxf(lmax, D);
    }
    #pragma unroll
    for (int o = 16; o > 0; o >>= 1)
        lmax = fmaxf(lmax, __shfl_xor_sync(0xffffffffu, lmax, o));
    if ((tid & 31) == 0) smax[tid >> 5] = lmax;
    __syncthreads();
    float Dmax = smax[0];
    #pragma unroll
    for (int w = 1; w < 8; w++) Dmax = fmaxf(Dmax, smax[w]);

    for (int j = tid; j < Lq; j += 256) {
        float m2 = mi * mask[b*Lq + j];
        sD[j] += 2.f * (1.f - m2) * Dmax;
    }
    __syncthreads();

    for (int k = 0; k < Kq; k++) {
        unsigned long long best = 0xffffffffffffffffull;
        for (int j = tid; j < Lq; j += 256) {
            unsigned long long p =
                (((unsigned long long)__float_as_uint(sD[j])) << 32) | (unsigned)j;
            best = (p < best) ? p : best;
        }
        #pragma unroll
        for (int o = 16; o > 0; o >>= 1) {
            unsigned long long other = __shfl_xor_sync(0xffffffffu, best, o);
            best = (other < best) ? other : best;
        }
        if ((tid & 31) == 0) red[tid >> 5] = best;
        __syncthreads();
        if (tid == 0) {
            unsigned long long bb = red[0];
            #pragma unroll
            for (int w = 1; w < 8; w++) bb = (red[w] < bb) ? red[w] : bb;
            int j = (int)(bb & 0xffffffffull);
            g_Eidx[bi*Kq + k] = j;
            if (outIdxF) outIdxF[bi*Kq + k] = (float)j;
            sD[j] = __int_as_float(0x7f800000);
        }
        __syncthreads();
    }
}

// ---------------------------------------------------------------------------
__device__ __forceinline__ void loadX2(const float* __restrict__ Xres, int a, float* out3) {
    if (a == 4) {  // virtual Cb
        float Nx = Xres[0], Ny = Xres[1], Nz = Xres[2];
        float Cax= Xres[3], Cay= Xres[4], Caz= Xres[5];
        float Cx = Xres[6], Cy = Xres[7], Cz = Xres[8];
        float bx = Cax - Nx, by = Cay - Ny, bz = Caz - Nz;
        float cx = Cx - Cax, cy = Cy - Cay, cz = Cz - Caz;
        float ax = by*cz - bz*cy;
        float ay = bz*cx - bx*cz;
        float az = bx*cy - by*cx;
        out3[0] = -0.58273431f*ax + 0.56802827f*bx - 0.54067466f*cx + Cax;
        out3[1] = -0.58273431f*ay + 0.56802827f*by - 0.54067466f*cy + Cay;
        out3[2] = -0.58273431f*az + 0.56802827f*bz - 0.54067466f*cz + Caz;
    } else {
        out3[0] = Xres[a*3+0];
        out3[1] = Xres[a*3+1];
        out3[2] = Xres[a*3+2];
    }
}

// ---------------------------------------------------------------------------
// Consume one chunk: thread owns 4 features (lt + 32q) and e-pairs
// [EP0, EP0+NEP). F values hoisted to registers per pass; features iterated
// innermost so only one feature's 4 W-ull are live at a time.
// acc layout: acc[q*4 + ei]
// ---------------------------------------------------------------------------
template<int NEP>
__device__ __forceinline__ void consume_chunk4(
    const float* __restrict__ FaBase, int EP0,
    const float4* __restrict__ Wrow,   // &g_W4[kq0*EFq + lt]
    ull* __restrict__ acc)
{
    #pragma unroll
    for (int p = 0; p < 4; p++) {
        // hoist F for my eps (broadcast LDS.128 x2 per ep, reused by 4 features)
        ulonglong2 qa[NEP], qb[NEP];
        #pragma unroll
        for (int ei = 0; ei < NEP; ei++) {
            const ulonglong2* m =
                (const ulonglong2*)(FaBase + (EP0+ei)*PADF) + 2*p;
            qa[ei] = m[0];
            qb[ei] = m[1];
        }
        #pragma unroll
        for (int q = 0; q < 4; q++) {
            float4 v = Wrow[p*EFq + 32*q];
            ull W0 = rep2(v.x), W1 = rep2(v.y), W2 = rep2(v.z), W3 = rep2(v.w);
            #pragma unroll
            for (int ei = 0; ei < NEP; ei++) {
                ull t = fma2(qa[ei].x, W0, acc[q*4 + ei]);
                t = fma2(qa[ei].y, W1, t);
                t = fma2(qb[ei].x, W2, t);
                t = fma2(qb[ei].y, W3, t);
                acc[q*4 + ei] = t;
            }
        }
    }
}

// ---------------------------------------------------------------------------
// Fused edge kernel: 4 features/thread, e-pairs split across 4 warps.
//   warp w (w=0..2): e-pairs 4w..4w+3 ; warp 3: e-pairs 12..14
//   lane lt: features lt, lt+32, lt+64, lt+96
// __launch_bounds__(128,5): cap regs ~102 -> 5 warps/SMSP residency.
// ---------------------------------------------------------------------------
__global__ __launch_bounds__(128, 5) void edge_kernel(
    const float* __restrict__ X,
    const float* __restrict__ atom_mask,
    const float* __restrict__ gamma,
    const float* __restrict__ beta,
    float* __restrict__ outE) {

    const int bi = blockIdx.x;
    const int b  = bi / Lq, i = bi % Lq;
    const int tid = threadIdx.x;

    const int wgrp = tid >> 5;
    const int lt   = tid & 31;
    const int myEP0 = wgrp * 4;
    const int myNEP = (wgrp == 3) ? 3 : 4;

    __shared__ __align__(16) float FaU[3840];     // F half-slab / LN acc buffer
    __shared__ __align__(16) float Epos[Kq][NPEq];
    __shared__ float X2n[Kq][Aq][3];
    __shared__ float amn[Kq][Aq];
    __shared__ float X2i[Aq][3];
    __shared__ float ami[Aq];
    __shared__ int   jn[Kq];
    __shared__ float sg[EFq], sb[EFq];
    __shared__ int   alist[Aq];
    __shared__ int   nact;

    if (tid < Kq) jn[tid] = g_Eidx[bi*Kq + tid];
    if (tid < Aq) {
        loadX2(X + bi*Aq*3, tid, X2i[tid]);
        ami[tid] = 1.0f - atom_mask[bi*Aq + tid];
    }
    sg[tid] = gamma[tid];
    sb[tid] = beta[tid];
    __syncthreads();

    for (int t = tid; t < Kq*Aq; t += 128) {
        int e = t / Aq, a = t % Aq;
        int j = jn[e];
        loadX2(X + (b*Lq + j)*Aq*3, a, X2n[e][a]);
        amn[e][a] = 1.0f - atom_mask[(b*Lq + j)*Aq + a];
    }
    for (int t = tid; t < Kq*NPEq; t += 128) {
        int e = t / NPEq, p = t % NPEq;
        float d  = (float)jn[e] - (float)i;
        int   pp = p & 7;
        float fr = expf((float)(2*pp) * -0.57564627324851148f); // -ln(1e4)/16
        float ang = d * fr;
        Epos[e][p] = (p < 8) ? cosf(ang) : sinf(ang);
    }
    if (tid == 0) {
        int c = 0;
        #pragma unroll
        for (int a = 0; a < Aq; a++) if (ami[a] != 0.f) alist[c++] = a;
        nact = c;
    }
    __syncthreads();

    // ---- PE chunk: init acc for my eps x 4 features (one-time, scalar) ----
    ull acc[16];
    #pragma unroll
    for (int ei = 0; ei < 4; ei++) {
        #pragma unroll
        for (int q = 0; q < 4; q++) acc[q*4+ei] = 0;
        if (ei < myNEP) {
            #pragma unroll
            for (int q = 0; q < 4; q++) {
                float pv[2];
                #pragma unroll
                for (int h = 0; h < 2; h++) {
                    const float* vp = Epos[2*(myEP0+ei) + h];
                    float s = 0.f;
                    #pragma unroll
                    for (int kq = 0; kq < 4; kq++) {
                        float4 v = g_W4[kq*EFq + lt + 32*q];
                        s = fmaf(v.x, vp[4*kq+0], s);
                        s = fmaf(v.y, vp[4*kq+1], s);
                        s = fmaf(v.z, vp[4*kq+2], s);
                        s = fmaf(v.w, vp[4*kq+3], s);
                    }
                    pv[h] = s;
                }
                acc[q*4+ei] = pack2(pv[0], pv[1]);
            }
        }
    }

    // ---- main flat chunk loop ----
    const int nchunks = nact * Aq;
    for (int ci = 0; ci < nchunks; ci++) {
        const int ai = ci / Aq;
        const int a  = alist[ai];
        const int b2 = ci - ai * Aq;

        if (b2 == 0 || b2 == 7) {
            __syncthreads();          // previous consume of FaU finished
            if (tid < 105) {
                const int ep  = tid / 7;
                const int b2l = tid % 7;
                const int b2g = ((b2 >= 7) ? 7 : 0) + b2l;
                const float xa0 = X2i[a][0], xa1 = X2i[a][1], xa2 = X2i[a][2];
                const int e0 = 2*ep, e1 = e0 + 1;
                const float act0 = amn[e0][b2g];
                const float act1 = amn[e1][b2g];
                float dx = xa0 - X2n[e0][b2g][0];
                float dy = xa1 - X2n[e0][b2g][1];
                float dz = xa2 - X2n[e0][b2g][2];
                const float D0 = sqrtf(dx*dx + dy*dy + dz*dz + 1e-6f);
                dx = xa0 - X2n[e1][b2g][0];
                dy = xa1 - X2n[e1][b2g][1];
                dz = xa2 - X2n[e1][b2g][2];
                const float D1 = sqrtf(dx*dx + dy*dy + dz*dz + 1e-6f);
                float* slot = &FaU[(b2l*15 + ep)*PADF];
                #pragma unroll
                for (int rr = 0; rr < NRBF; rr++) {
                    const int r = (rr + tid) & 15;       // bank rotation
                    const float mu = (float)r * (20.f/15.f);
                    float x0 = (D0 - mu) * 0.8f;
                    float x1 = (D1 - mu) * 0.8f;
                    float v0 = __expf(-x0*x0) * act0;
                    float v1 = __expf(-x1*x1) * act1;
                    *(float2*)(slot + 2*r) = make_float2(v0, v1);
                }
            }
            __syncthreads();
        }

        const int kq0 = 4 + (a*Aq + b2)*4;
        const float4* Wrow = &g_W4[kq0*EFq + lt];

        const int b2l = (b2 >= 7) ? (b2 - 7) : b2;
        const float* FaBase = &FaU[b2l * 15 * PADF];
        if (wgrp == 3) consume_chunk4<3>(FaBase, myEP0, Wrow, acc);
        else           consume_chunk4<4>(FaBase, myEP0, Wrow, acc);
    }

    // ---- dump acc pairs to smem (reusing FaU), then LayerNorm ----
    __syncthreads();
    #pragma unroll
    for (int ei = 0; ei < 4; ei++) {
        if (ei < myNEP) {
            const int ep = myEP0 + ei;
            #pragma unroll
            for (int q = 0; q < 4; q++) {
                float lo, hi;
                unpack2(acc[q*4+ei], lo, hi);
                *(float2*)&FaU[(ep*EFq + lt + 32*q)*2] = make_float2(lo, hi);
            }
        }
    }
    __syncthreads();

    const int wid = tid >> 5, lid = tid & 31;
    float* outRow = outE + (size_t)bi * (Kq*EFq);
    for (int e = wid; e < Kq; e += 4) {
        const int ep = e >> 1, par = e & 1;
        const float* ab = &FaU[ep*EFq*2 + par];
        float v0 = ab[(lid      )*2];
        float v1 = ab[(lid + 32 )*2];
        float v2 = ab[(lid + 64 )*2];
        float v3 = ab[(lid + 96 )*2];
        float s  = (v0 + v1) + (v2 + v3);
        float sq = fmaf(v0,v0, fmaf(v1,v1, fmaf(v2,v2, v3*v3)));
        #pragma unroll
        for (int o = 16; o > 0; o >>= 1) {
            s  += __shfl_xor_sync(0xffffffffu, s,  o);
            sq += __shfl_xor_sync(0xffffffffu, sq, o);
        }
        float mean = s * (1.f/EFq);
        float var  = sq * (1.f/EFq) - mean*mean;
        float rstd = rsqrtf(var + 1e-5f);
        float* o0 = outRow + e*EFq;
        o0[lid     ] = (v0 - mean) * rstd * sg[lid     ] + sb[lid     ];
        o0[lid + 32] = (v1 - mean) * rstd * sg[lid + 32] + sb[lid + 32];
        o0[lid + 64] = (v2 - mean) * rstd * sg[lid + 64] + sb[lid + 64];
        o0[lid + 96] = (v3 - mean) * rstd * sg[lid + 96] + sb[lid + 96];
    }
}

// ---------------------------------------------------------------------------
extern "C" void kernel_launch(void* const* d_in, const int* in_sizes, int n_in,
                              void* d_out, int out_size) {
    const float* X         = (const float*)d_in[0];
    const float* mask      = (const float*)d_in[1];
    const float* atom_mask = (const float*)d_in[4];
    const float* W         = (const float*)d_in[5];
    const float* gamma     = (const float*)d_in[6];
    const float* beta      = (const float*)d_in[7];

    float* outE   = (float*)d_out;
    float* outIdx = (out_size >= NE + NK) ? (outE + NE) : nullptr;

    prep_kernel<<<NPACKBLK + Bq*Lq, 256>>>(W, X, mask, outIdx);
    edge_kernel<<<Bq*Lq, 128>>>(X, atom_mask, gamma, beta, outE);
}